// round 9
// baseline (speedup 1.0000x reference)
#include <cuda_runtime.h>
#include <cuda_fp16.h>
#include <cstdint>
#include <cstddef>

// ---------------- problem constants ----------------
#define T_TOK 4096
#define D_DIM 1024
#define F_DIM 2816
#define F2_DIM 5632
#define N_EXP 8
#define TK 8192

// ---------------- tiling ----------------
// fp16: BM=128, BN=64, BK=64 (128B rows), 256 threads, warps 2m x 2n x 2k
// (each warp: 64m x 32n, two k16 steps per stage), 3-stage cp.async, 2 CTAs/SM.
#define N_ST 3
#define A_ST 16384                     // 128 rows * 128 B
#define B_ST 8192                      // 64 rows * 128 B
#define STAGE_BYTES (A_ST + B_ST)      // 24 KB
#define SMEM_BYTES (N_ST * STAGE_BYTES)  // 72 KB
#define GRIDX 9

// ---------------- device scratch ----------------
__device__ int    g_offsets[N_EXP + 1];
__device__ int    g_tok[TK];
__device__ int    g_pos[TK];
__device__ float  g_wt[TK];
__device__ __half g_xh[(size_t)T_TOK * D_DIM];
__device__ __half g_wguh[(size_t)N_EXP * F2_DIM * D_DIM];
__device__ __half g_wdh[(size_t)N_EXP * D_DIM * F_DIM];
__device__ __half g_h[(size_t)TK * F_DIM];
__device__ float  g_o[(size_t)TK * D_DIM];

// ---------------- helpers ----------------
__device__ __forceinline__ uint32_t cvta_s(const void* p) {
    return (uint32_t)__cvta_generic_to_shared(p);
}
__device__ __forceinline__ void cpasync16(uint32_t smem_addr, const void* gptr) {
    asm volatile("cp.async.cg.shared.global [%0], [%1], 16;" ::"r"(smem_addr), "l"(gptr));
}
__device__ __forceinline__ void cp_commit() { asm volatile("cp.async.commit_group;"); }
__device__ __forceinline__ void cp_wait0() { asm volatile("cp.async.wait_group 0;"); }
__device__ __forceinline__ void cp_wait1() { asm volatile("cp.async.wait_group 1;"); }
__device__ __forceinline__ void ldsm4(uint32_t r[4], uint32_t addr) {
    asm volatile("ldmatrix.sync.aligned.m8n8.x4.shared.b16 {%0,%1,%2,%3}, [%4];"
                 : "=r"(r[0]), "=r"(r[1]), "=r"(r[2]), "=r"(r[3]) : "r"(addr));
}
__device__ __forceinline__ void mma_f16(float c[4], const uint32_t a[4],
                                        uint32_t b0, uint32_t b1) {
    asm volatile(
        "mma.sync.aligned.m16n8k16.row.col.f32.f16.f16.f32 "
        "{%0,%1,%2,%3},{%4,%5,%6,%7},{%8,%9},{%0,%1,%2,%3};"
        : "+f"(c[0]), "+f"(c[1]), "+f"(c[2]), "+f"(c[3])
        : "r"(a[0]), "r"(a[1]), "r"(a[2]), "r"(a[3]), "r"(b0), "r"(b1));
}

// ---------------- convert f32 inputs to fp16 ----------------
__global__ void cvt_all(const float4* __restrict__ x, const float4* __restrict__ wgu,
                        const float4* __restrict__ wd) {
    const int NX = T_TOK * D_DIM / 4;
    const int NG = N_EXP * F2_DIM * D_DIM / 4;
    const int ND = N_EXP * D_DIM * F_DIM / 4;
    const int total = NX + NG + ND;
    for (int i = blockIdx.x * blockDim.x + threadIdx.x; i < total;
         i += gridDim.x * blockDim.x) {
        const float4* s;
        __half2* d;
        int j;
        if (i < NX)           { s = x;   d = (__half2*)g_xh;   j = i; }
        else if (i < NX + NG) { s = wgu; d = (__half2*)g_wguh; j = i - NX; }
        else                  { s = wd;  d = (__half2*)g_wdh;  j = i - NX - NG; }
        float4 v = s[j];
        d[2 * j]     = __float22half2_rn(make_float2(v.x, v.y));
        d[2 * j + 1] = __float22half2_rn(make_float2(v.z, v.w));
    }
}

// ---------------- routing ----------------
__global__ void routing_kernel(const void* sel_raw, const float* __restrict__ rw) {
    __shared__ int sc[N_EXP];
    __shared__ int scur[N_EXP];
    __shared__ int smode;
    int tid = threadIdx.x;
    if (tid < N_EXP) sc[tid] = 0;
    if (tid == 0) {
        const int* s32 = (const int*)sel_raw;
        int any = 0;
        #pragma unroll
        for (int i = 0; i < 8; i++) any |= s32[2 * i + 1];
        smode = any ? 0 : 1;  // 1 = int64
    }
    __syncthreads();
    int mode = smode;
    const long long* s64 = (const long long*)sel_raw;
    const int* s32 = (const int*)sel_raw;
    for (int i = tid; i < TK; i += blockDim.x) {
        int e = mode ? (int)s64[i] : s32[i];
        atomicAdd(&sc[e], 1);
    }
    __syncthreads();
    if (tid == 0) {
        int off = 0;
        for (int e = 0; e < N_EXP; e++) { g_offsets[e] = off; scur[e] = off; off += sc[e]; }
        g_offsets[N_EXP] = off;
    }
    __syncthreads();
    for (int i = tid; i < TK; i += blockDim.x) {
        int e = mode ? (int)s64[i] : s32[i];
        int p = atomicAdd(&scur[e], 1);
        g_tok[p] = i >> 1;
        g_pos[p] = i;
        g_wt[p] = rw[i];
    }
}

// ---------------- shared fp16 mainloop (BK=64) ----------------
// Stage: [A 16KB: 128 rows x 128B][B 8KB: 64 rows x 128B].
// Swizzle: 16B chunk c (0..7) of row r at r*128 + ((c ^ (r&7))<<4).
// Warp (wk=warp>>2, wm=(warp>>1)&1, wn=warp&1): 64m x 32n, k16 steps 2wk+{0,1}.
__device__ __forceinline__ void mma_loop(uint32_t smem0, const __half* a_row,
                                         const __half* b_row, int KT64,
                                         float cc[4][4][4]) {
    const int tid = threadIdx.x;
    const int lane = tid & 31;
    const int warp = tid >> 5;
    const int wk = warp >> 2;
    const int wm = (warp >> 1) & 1;
    const int wn = warp & 1;

    // loaders: A row = tid>>1 (4 chunks), B row = tid>>2 (2 chunks)
    const int ra = tid >> 1;
    const int rb = tid >> 2;
    uint32_t stA[4], stB[2];
    #pragma unroll
    for (int i = 0; i < 4; i++) {
        const int c = (tid & 1) * 4 + i;
        stA[i] = (uint32_t)(ra * 128) + (uint32_t)(((c ^ (ra & 7)) << 4));
    }
    #pragma unroll
    for (int i = 0; i < 2; i++) {
        const int c = (tid & 3) * 2 + i;
        stB[i] = (uint32_t)(A_ST + rb * 128) + (uint32_t)(((c ^ (rb & 7)) << 4));
    }

    // ldsm bases (stage-relative)
    const int arow_l = (lane & 7) + (lane & 8);            // 0..15
    const int brow_l = (lane & 7) + ((lane >> 4) << 3);    // 0..15
    uint32_t a_base[4], b_base[2];
    #pragma unroll
    for (int mt = 0; mt < 4; mt++)
        a_base[mt] = (uint32_t)((wm * 64 + mt * 16 + arow_l) * 128);
    #pragma unroll
    for (int n2 = 0; n2 < 2; n2++)
        b_base[n2] = (uint32_t)(A_ST + (wn * 32 + n2 * 16 + brow_l) * 128);
    const uint32_t axr = (uint32_t)((lane >> 4) ^ (arow_l & 7));        // chunk-lsb ^ row&7
    const uint32_t bxr = (uint32_t)(((lane >> 3) & 1) ^ (brow_l & 7));

    auto load_stage = [&](int kt) {
        const uint32_t sb = smem0 + (uint32_t)((kt % N_ST) * STAGE_BYTES);
        const __half* As = a_row + kt * 64;
        const __half* Bs = b_row + kt * 64;
        #pragma unroll
        for (int i = 0; i < 4; i++)
            cpasync16(sb + stA[i], As + ((tid & 1) * 4 + i) * 8);
        #pragma unroll
        for (int i = 0; i < 2; i++)
            cpasync16(sb + stB[i], Bs + ((tid & 3) * 2 + i) * 8);
        cp_commit();
    };

    load_stage(0);
    if (KT64 > 1) load_stage(1);

    for (int kt = 0; kt < KT64; kt++) {
        if (kt + 1 < KT64) cp_wait1(); else cp_wait0();
        __syncthreads();
        if (kt + 2 < KT64) load_stage(kt + 2);

        const uint32_t base = smem0 + (uint32_t)((kt % N_ST) * STAGE_BYTES);
        #pragma unroll
        for (int kk = 0; kk < 2; kk++) {
            const uint32_t cb2 = (uint32_t)((4 * wk + 2 * kk));  // chunk base of k16 step
            const uint32_t swA = ((cb2 ^ axr) << 4);
            const uint32_t swB = ((cb2 ^ bxr) << 4);
            uint32_t a[4][4], b[2][4];
            #pragma unroll
            for (int mt = 0; mt < 4; mt++)
                ldsm4(a[mt], base + a_base[mt] + swA);
            #pragma unroll
            for (int n2 = 0; n2 < 2; n2++)
                ldsm4(b[n2], base + b_base[n2] + swB);
            #pragma unroll
            for (int mt = 0; mt < 4; mt++)
                #pragma unroll
                for (int nt = 0; nt < 4; nt++)
                    mma_f16(cc[mt][nt], a[mt], b[nt >> 1][(nt & 1) * 2],
                            b[nt >> 1][(nt & 1) * 2 + 1]);
        }
    }

    // k-split reduction: warp pairs (w, w+4) share (wm, wn); 8KB slot each.
    __syncthreads();
    const uint32_t redb = smem0 + (uint32_t)((warp & 3) * 8192);
    if (wk == 1) {
        #pragma unroll
        for (int mt = 0; mt < 4; mt++)
            #pragma unroll
            for (int nt = 0; nt < 4; nt++) {
                uint32_t addr = redb + (uint32_t)(((mt * 4 + nt) * 32 + lane) * 16);
                asm volatile("st.shared.v4.b32 [%0], {%1,%2,%3,%4};" ::"r"(addr),
                             "r"(__float_as_uint(cc[mt][nt][0])),
                             "r"(__float_as_uint(cc[mt][nt][1])),
                             "r"(__float_as_uint(cc[mt][nt][2])),
                             "r"(__float_as_uint(cc[mt][nt][3])) : "memory");
            }
    }
    __syncthreads();
    if (wk == 0) {
        #pragma unroll
        for (int mt = 0; mt < 4; mt++)
            #pragma unroll
            for (int nt = 0; nt < 4; nt++) {
                uint32_t addr = redb + (uint32_t)(((mt * 4 + nt) * 32 + lane) * 16);
                uint32_t r0, r1, r2, r3;
                asm volatile("ld.shared.v4.b32 {%0,%1,%2,%3}, [%4];"
                             : "=r"(r0), "=r"(r1), "=r"(r2), "=r"(r3) : "r"(addr));
                cc[mt][nt][0] += __uint_as_float(r0);
                cc[mt][nt][1] += __uint_as_float(r1);
                cc[mt][nt][2] += __uint_as_float(r2);
                cc[mt][nt][3] += __uint_as_float(r3);
            }
    }
    __syncthreads();  // reduce reads done before next row-block's loads
}

// ---------------- GEMM1: X @ Wgu^T (+SwiGLU) -> g_h (fp16) ----------------
// B rows interleave gate/up by parity (64 B-rows = 32 h-cols).
__global__ void __launch_bounds__(256, 2)
gemm1_k() {
    const int e = blockIdx.z;
    const int base = g_offsets[e];
    const int n_e = g_offsets[e + 1] - base;
    const int col0 = blockIdx.y * 32;  // h columns per tile

    extern __shared__ __align__(128) char smraw[];
    const uint32_t smem0 = cvta_s(smraw);
    const int tid = threadIdx.x;
    const int lane = tid & 31, warp = tid >> 5;
    const int wk = warp >> 2;
    const int wm = (warp >> 1) & 1, wn = warp & 1;

    const int nrow = tid >> 2;
    const int wrow = col0 + (nrow >> 1) + ((nrow & 1) ? F_DIM : 0);
    const __half* b_row = g_wguh + ((size_t)e * F2_DIM + wrow) * D_DIM;

    for (int rb2 = blockIdx.x; rb2 * 128 < n_e; rb2 += GRIDX) {
        const int row0 = rb2 * 128;
        int ge = base + row0 + (tid >> 1);
        if (ge > TK - 1) ge = TK - 1;
        const __half* a_row = g_xh + (size_t)g_tok[ge] * D_DIM;

        float cc[4][4][4];
        #pragma unroll
        for (int a = 0; a < 4; a++)
            #pragma unroll
            for (int b = 0; b < 4; b++)
                #pragma unroll
                for (int c = 0; c < 4; c++) cc[a][b][c] = 0.f;

        mma_loop(smem0, a_row, b_row, D_DIM / 64, cc);

        if (wk == 0) {
            const int rbase = wm * 64 + (lane >> 2);
            const int jbase = col0 + wn * 16 + (lane & 3);
            #pragma unroll
            for (int mt = 0; mt < 4; mt++) {
                const int r0 = rbase + mt * 16;
                #pragma unroll
                for (int nt = 0; nt < 4; nt++) {
                    const int j = jbase + (nt >> 1) * 8 + (nt & 1) * 4;
                    if (row0 + r0 < n_e) {
                        float g = cc[mt][nt][0], u = cc[mt][nt][1];
                        float h = g * u / (1.f + __expf(-g));
                        g_h[(size_t)(base + row0 + r0) * F_DIM + j] = __float2half_rn(h);
                    }
                    if (row0 + r0 + 8 < n_e) {
                        float g = cc[mt][nt][2], u = cc[mt][nt][3];
                        float h = g * u / (1.f + __expf(-g));
                        g_h[(size_t)(base + row0 + r0 + 8) * F_DIM + j] = __float2half_rn(h);
                    }
                }
            }
        }
    }
}

// ---------------- GEMM2: g_h @ Wd^T, scale, per-slot store ----------------
__global__ void __launch_bounds__(256, 2)
gemm2_k() {
    const int e = blockIdx.z;
    const int base = g_offsets[e];
    const int n_e = g_offsets[e + 1] - base;
    const int col0 = blockIdx.y * 64;  // over D

    extern __shared__ __align__(128) char smraw[];
    const uint32_t smem0 = cvta_s(smraw);
    const int tid = threadIdx.x;
    const int lane = tid & 31, warp = tid >> 5;
    const int wk = warp >> 2;
    const int wm = (warp >> 1) & 1, wn = warp & 1;

    const __half* b_row = g_wdh + ((size_t)e * D_DIM + col0 + (tid >> 2)) * F_DIM;

    for (int rb2 = blockIdx.x; rb2 * 128 < n_e; rb2 += GRIDX) {
        const int row0 = rb2 * 128;
        int ge = base + row0 + (tid >> 1);
        if (ge > TK - 1) ge = TK - 1;
        const __half* a_row = g_h + (size_t)ge * F_DIM;

        float cc[4][4][4];
        #pragma unroll
        for (int a = 0; a < 4; a++)
            #pragma unroll
            for (int b = 0; b < 4; b++)
                #pragma unroll
                for (int c = 0; c < 4; c++) cc[a][b][c] = 0.f;

        mma_loop(smem0, a_row, b_row, F_DIM / 64, cc);

        if (wk == 0) {
            const int rbase = wm * 64 + (lane >> 2);
            const int colb = col0 + wn * 32 + 2 * (lane & 3);
            #pragma unroll
            for (int mt = 0; mt < 4; mt++) {
                const int r0 = rbase + mt * 16;
                #pragma unroll
                for (int half = 0; half < 2; half++) {
                    const int r = r0 + half * 8;
                    if (row0 + r < n_e) {
                        const int gi = base + row0 + r;
                        const int pos = g_pos[gi];
                        const float wt = g_wt[gi];
                        float* orow = g_o + (size_t)pos * D_DIM;
                        #pragma unroll
                        for (int nt = 0; nt < 4; nt++) {
                            const int col = colb + (nt >> 1) * 16 + (nt & 1) * 8;
                            float2 v;
                            v.x = cc[mt][nt][half * 2 + 0] * wt;
                            v.y = cc[mt][nt][half * 2 + 1] * wt;
                            *(float2*)(orow + col) = v;
                        }
                    }
                }
            }
        }
    }
}

// ---------------- combine the 2 slots per token ----------------
__global__ void combine_kernel(float4* __restrict__ out) {
    const int RD = D_DIM / 4;
    int i = blockIdx.x * blockDim.x + threadIdx.x;
    if (i < T_TOK * RD) {
        int t = i / RD, r = i % RD;
        const float4* go = (const float4*)g_o;
        float4 a = go[(size_t)(2 * t) * RD + r];
        float4 b = go[(size_t)(2 * t + 1) * RD + r];
        out[i] = make_float4(a.x + b.x, a.y + b.y, a.z + b.z, a.w + b.w);
    }
}

// ---------------- launch ----------------
extern "C" void kernel_launch(void* const* d_in, const int* in_sizes, int n_in,
                              void* d_out, int out_size) {
    const float* X   = (const float*)d_in[0];
    const float* rw  = (const float*)d_in[1];
    const float* Wgu = (const float*)d_in[2];
    const float* Wd  = (const float*)d_in[3];
    const void*  sel = d_in[4];
    float* out = (float*)d_out;

    cudaFuncSetAttribute(gemm1_k, cudaFuncAttributeMaxDynamicSharedMemorySize, SMEM_BYTES);
    cudaFuncSetAttribute(gemm2_k, cudaFuncAttributeMaxDynamicSharedMemorySize, SMEM_BYTES);

    cvt_all<<<2048, 256>>>((const float4*)X, (const float4*)Wgu, (const float4*)Wd);
    routing_kernel<<<1, 1024>>>(sel, rw);
    gemm1_k<<<dim3(GRIDX, F_DIM / 32, N_EXP), 256, SMEM_BYTES>>>();
    gemm2_k<<<dim3(GRIDX, D_DIM / 64, N_EXP), 256, SMEM_BYTES>>>();
    combine_kernel<<<(T_TOK * D_DIM / 4 + 255) / 256, 256>>>((float4*)out);
}

// round 10
// speedup vs baseline: 1.1829x; 1.1829x over previous
#include <cuda_runtime.h>
#include <cuda_fp16.h>
#include <cstdint>
#include <cstddef>

// ---------------- problem constants ----------------
#define T_TOK 4096
#define D_DIM 1024
#define F_DIM 2816
#define F2_DIM 5632
#define N_EXP 8
#define TK 8192

// ---------------- tiling ----------------
// fp16: BM=128, BN=64, BK=32, 256 threads, warps 2m x 2n x 2k
// (warp tile 64m x 32n x k16 via m16n8k16), 6-stage cp.async (5 in flight),
// 2 CTAs/SM.
#define N_ST 6
#define A_ST 8192                      // 128 rows * 64 B
#define B_ST 4096                      // 64 rows * 64 B
#define STAGE_BYTES (A_ST + B_ST)      // 12 KB
#define SMEM_BYTES (N_ST * STAGE_BYTES)  // 72 KB
#define GRIDX 9

// ---------------- device scratch ----------------
__device__ int    g_offsets[N_EXP + 1];
__device__ int    g_tok[TK];
__device__ int    g_pos[TK];
__device__ float  g_wt[TK];
__device__ __half g_xh[(size_t)T_TOK * D_DIM];
__device__ __half g_wguh[(size_t)N_EXP * F2_DIM * D_DIM];
__device__ __half g_wdh[(size_t)N_EXP * D_DIM * F_DIM];
__device__ __half g_h[(size_t)TK * F_DIM];
__device__ float  g_o[(size_t)TK * D_DIM];

// ---------------- helpers ----------------
__device__ __forceinline__ uint32_t cvta_s(const void* p) {
    return (uint32_t)__cvta_generic_to_shared(p);
}
__device__ __forceinline__ void cpasync16(uint32_t smem_addr, const void* gptr) {
    asm volatile("cp.async.cg.shared.global [%0], [%1], 16;" ::"r"(smem_addr), "l"(gptr));
}
__device__ __forceinline__ void cp_commit() { asm volatile("cp.async.commit_group;"); }
__device__ __forceinline__ void cp_waitg(int left) {
    if (left <= 0) asm volatile("cp.async.wait_group 0;");
    else if (left == 1) asm volatile("cp.async.wait_group 1;");
    else if (left == 2) asm volatile("cp.async.wait_group 2;");
    else if (left == 3) asm volatile("cp.async.wait_group 3;");
    else asm volatile("cp.async.wait_group 4;");
}
__device__ __forceinline__ void ldsm4(uint32_t r[4], uint32_t addr) {
    asm volatile("ldmatrix.sync.aligned.m8n8.x4.shared.b16 {%0,%1,%2,%3}, [%4];"
                 : "=r"(r[0]), "=r"(r[1]), "=r"(r[2]), "=r"(r[3]) : "r"(addr));
}
__device__ __forceinline__ void mma_f16(float c[4], const uint32_t a[4],
                                        uint32_t b0, uint32_t b1) {
    asm volatile(
        "mma.sync.aligned.m16n8k16.row.col.f32.f16.f16.f32 "
        "{%0,%1,%2,%3},{%4,%5,%6,%7},{%8,%9},{%0,%1,%2,%3};"
        : "+f"(c[0]), "+f"(c[1]), "+f"(c[2]), "+f"(c[3])
        : "r"(a[0]), "r"(a[1]), "r"(a[2]), "r"(a[3]), "r"(b0), "r"(b1));
}

// ---------------- convert f32 inputs to fp16 ----------------
__global__ void cvt_all(const float4* __restrict__ x, const float4* __restrict__ wgu,
                        const float4* __restrict__ wd) {
    const int NX = T_TOK * D_DIM / 4;
    const int NG = N_EXP * F2_DIM * D_DIM / 4;
    const int ND = N_EXP * D_DIM * F_DIM / 4;
    const int total = NX + NG + ND;
    for (int i = blockIdx.x * blockDim.x + threadIdx.x; i < total;
         i += gridDim.x * blockDim.x) {
        const float4* s;
        __half2* d;
        int j;
        if (i < NX)           { s = x;   d = (__half2*)g_xh;   j = i; }
        else if (i < NX + NG) { s = wgu; d = (__half2*)g_wguh; j = i - NX; }
        else                  { s = wd;  d = (__half2*)g_wdh;  j = i - NX - NG; }
        float4 v = s[j];
        d[2 * j]     = __float22half2_rn(make_float2(v.x, v.y));
        d[2 * j + 1] = __float22half2_rn(make_float2(v.z, v.w));
    }
}

// ---------------- routing ----------------
__global__ void routing_kernel(const void* sel_raw, const float* __restrict__ rw) {
    __shared__ int sc[N_EXP];
    __shared__ int scur[N_EXP];
    __shared__ int smode;
    int tid = threadIdx.x;
    if (tid < N_EXP) sc[tid] = 0;
    if (tid == 0) {
        const int* s32 = (const int*)sel_raw;
        int any = 0;
        #pragma unroll
        for (int i = 0; i < 8; i++) any |= s32[2 * i + 1];
        smode = any ? 0 : 1;  // 1 = int64
    }
    __syncthreads();
    int mode = smode;
    const long long* s64 = (const long long*)sel_raw;
    const int* s32 = (const int*)sel_raw;
    for (int i = tid; i < TK; i += blockDim.x) {
        int e = mode ? (int)s64[i] : s32[i];
        atomicAdd(&sc[e], 1);
    }
    __syncthreads();
    if (tid == 0) {
        int off = 0;
        for (int e = 0; e < N_EXP; e++) { g_offsets[e] = off; scur[e] = off; off += sc[e]; }
        g_offsets[N_EXP] = off;
    }
    __syncthreads();
    for (int i = tid; i < TK; i += blockDim.x) {
        int e = mode ? (int)s64[i] : s32[i];
        int p = atomicAdd(&scur[e], 1);
        g_tok[p] = i >> 1;
        g_pos[p] = i;
        g_wt[p] = rw[i];
    }
}

// ---------------- shared fp16 mainloop (BK=32, deep pipeline) ----------------
// Stage: [A 8KB: 128 rows x 64B][B 4KB: 64 rows x 64B].
// Swizzle: 16B chunk c of row r at r*64 + ((c ^ ((r>>1)&3))<<4).
// Warp (wk=warp>>2, wm=(warp>>1)&1, wn=warp&1): 64m x 32n over k-half wk (k16).
__device__ __forceinline__ void mma_loop(uint32_t smem0, const __half* a_row,
                                         const __half* b_row, int KT,
                                         float cc[4][4][4]) {
    const int tid = threadIdx.x;
    const int lane = tid & 31;
    const int warp = tid >> 5;
    const int wk = warp >> 2;
    const int wm = (warp >> 1) & 1;
    const int wn = warp & 1;

    // loader: A row = tid>>1 (2 chunks), B row = tid>>2 (1 chunk)
    const int ra = tid >> 1;
    const int rb = tid >> 2;
    uint32_t stA[2], stB;
    #pragma unroll
    for (int i = 0; i < 2; i++) {
        const int c = (tid & 1) * 2 + i;
        stA[i] = (uint32_t)(ra * 64) + (uint32_t)(((c ^ ((ra >> 1) & 3)) << 4));
    }
    {
        const int c = tid & 3;
        stB = (uint32_t)(A_ST + rb * 64) + (uint32_t)(((c ^ ((rb >> 1) & 3)) << 4));
    }

    // ldsm addresses (stage-relative)
    const int arow_l = (lane & 7) + (lane & 8);
    const int brow_l = (lane & 7) + ((lane >> 4) << 3);
    const int achunk = 2 * wk + (lane >> 4);
    const int bchunk = 2 * wk + ((lane >> 3) & 1);
    uint32_t a_off[4], b_off[2];
    #pragma unroll
    for (int mt = 0; mt < 4; mt++) {
        const int row = wm * 64 + mt * 16 + arow_l;
        a_off[mt] = (uint32_t)(row * 64) +
                    (uint32_t)(((achunk ^ ((arow_l >> 1) & 3)) << 4));
    }
    #pragma unroll
    for (int n2 = 0; n2 < 2; n2++) {
        const int row = wn * 32 + n2 * 16 + brow_l;
        b_off[n2] = (uint32_t)(A_ST + row * 64) +
                    (uint32_t)(((bchunk ^ ((brow_l >> 1) & 3)) << 4));
    }

    auto load_stage = [&](int kt) {
        const uint32_t sb = smem0 + (uint32_t)((kt % N_ST) * STAGE_BYTES);
        const __half* As = a_row + kt * 32;
        const __half* Bs = b_row + kt * 32;
        #pragma unroll
        for (int i = 0; i < 2; i++)
            cpasync16(sb + stA[i], As + ((tid & 1) * 2 + i) * 8);
        cpasync16(sb + stB, Bs + (tid & 3) * 8);
        cp_commit();
    };

    // preload 5 stages (KT >= 32 always here)
    #pragma unroll
    for (int s = 0; s < 5; s++) load_stage(s);

    for (int kt = 0; kt < KT; kt++) {
        const int rem = KT - 1 - kt;
        cp_waitg(rem < 4 ? rem : 4);
        __syncthreads();
        if (kt + 5 < KT) load_stage(kt + 5);

        const uint32_t base = smem0 + (uint32_t)((kt % N_ST) * STAGE_BYTES);
        uint32_t a[4][4], b[2][4];
        #pragma unroll
        for (int mt = 0; mt < 4; mt++)
            ldsm4(a[mt], base + a_off[mt]);
        #pragma unroll
        for (int n2 = 0; n2 < 2; n2++)
            ldsm4(b[n2], base + b_off[n2]);
        #pragma unroll
        for (int mt = 0; mt < 4; mt++)
            #pragma unroll
            for (int nt = 0; nt < 4; nt++)
                mma_f16(cc[mt][nt], a[mt], b[nt >> 1][(nt & 1) * 2],
                        b[nt >> 1][(nt & 1) * 2 + 1]);
    }

    // k-split reduction: warp pairs (w, w+4) share (wm, wn); 8KB slot each.
    __syncthreads();
    const uint32_t redb = smem0 + (uint32_t)((warp & 3) * 8192);
    if (wk == 1) {
        #pragma unroll
        for (int mt = 0; mt < 4; mt++)
            #pragma unroll
            for (int nt = 0; nt < 4; nt++) {
                uint32_t addr = redb + (uint32_t)(((mt * 4 + nt) * 32 + lane) * 16);
                asm volatile("st.shared.v4.b32 [%0], {%1,%2,%3,%4};" ::"r"(addr),
                             "r"(__float_as_uint(cc[mt][nt][0])),
                             "r"(__float_as_uint(cc[mt][nt][1])),
                             "r"(__float_as_uint(cc[mt][nt][2])),
                             "r"(__float_as_uint(cc[mt][nt][3])) : "memory");
            }
    }
    __syncthreads();
    if (wk == 0) {
        #pragma unroll
        for (int mt = 0; mt < 4; mt++)
            #pragma unroll
            for (int nt = 0; nt < 4; nt++) {
                uint32_t addr = redb + (uint32_t)(((mt * 4 + nt) * 32 + lane) * 16);
                uint32_t r0, r1, r2, r3;
                asm volatile("ld.shared.v4.b32 {%0,%1,%2,%3}, [%4];"
                             : "=r"(r0), "=r"(r1), "=r"(r2), "=r"(r3) : "r"(addr));
                cc[mt][nt][0] += __uint_as_float(r0);
                cc[mt][nt][1] += __uint_as_float(r1);
                cc[mt][nt][2] += __uint_as_float(r2);
                cc[mt][nt][3] += __uint_as_float(r3);
            }
    }
    __syncthreads();  // reduce reads done before next row-block's loads
}

// ---------------- GEMM1: X @ Wgu^T (+SwiGLU) -> g_h (fp16) ----------------
// B rows interleave gate/up by parity (64 B-rows = 32 h-cols).
__global__ void __launch_bounds__(256, 2)
gemm1_k() {
    const int e = blockIdx.z;
    const int base = g_offsets[e];
    const int n_e = g_offsets[e + 1] - base;
    const int col0 = blockIdx.y * 32;  // h columns per tile

    extern __shared__ __align__(128) char smraw[];
    const uint32_t smem0 = cvta_s(smraw);
    const int tid = threadIdx.x;
    const int lane = tid & 31, warp = tid >> 5;
    const int wk = warp >> 2;
    const int wm = (warp >> 1) & 1, wn = warp & 1;

    const int nrow = tid >> 2;
    const int wrow = col0 + (nrow >> 1) + ((nrow & 1) ? F_DIM : 0);
    const __half* b_row = g_wguh + ((size_t)e * F2_DIM + wrow) * D_DIM;

    for (int rb2 = blockIdx.x; rb2 * 128 < n_e; rb2 += GRIDX) {
        const int row0 = rb2 * 128;
        int ge = base + row0 + (tid >> 1);
        if (ge > TK - 1) ge = TK - 1;
        const __half* a_row = g_xh + (size_t)g_tok[ge] * D_DIM;

        float cc[4][4][4];
        #pragma unroll
        for (int a = 0; a < 4; a++)
            #pragma unroll
            for (int b = 0; b < 4; b++)
                #pragma unroll
                for (int c = 0; c < 4; c++) cc[a][b][c] = 0.f;

        mma_loop(smem0, a_row, b_row, D_DIM / 32, cc);

        if (wk == 0) {
            const int rbase = wm * 64 + (lane >> 2);
            const int jbase = col0 + wn * 16 + (lane & 3);
            #pragma unroll
            for (int mt = 0; mt < 4; mt++) {
                const int r0 = rbase + mt * 16;
                #pragma unroll
                for (int nt = 0; nt < 4; nt++) {
                    const int j = jbase + (nt >> 1) * 8 + (nt & 1) * 4;
                    if (row0 + r0 < n_e) {
                        float g = cc[mt][nt][0], u = cc[mt][nt][1];
                        float h = g * u / (1.f + __expf(-g));
                        g_h[(size_t)(base + row0 + r0) * F_DIM + j] = __float2half_rn(h);
                    }
                    if (row0 + r0 + 8 < n_e) {
                        float g = cc[mt][nt][2], u = cc[mt][nt][3];
                        float h = g * u / (1.f + __expf(-g));
                        g_h[(size_t)(base + row0 + r0 + 8) * F_DIM + j] = __float2half_rn(h);
                    }
                }
            }
        }
    }
}

// ---------------- GEMM2: g_h @ Wd^T, scale, per-slot store ----------------
__global__ void __launch_bounds__(256, 2)
gemm2_k() {
    const int e = blockIdx.z;
    const int base = g_offsets[e];
    const int n_e = g_offsets[e + 1] - base;
    const int col0 = blockIdx.y * 64;  // over D

    extern __shared__ __align__(128) char smraw[];
    const uint32_t smem0 = cvta_s(smraw);
    const int tid = threadIdx.x;
    const int lane = tid & 31, warp = tid >> 5;
    const int wk = warp >> 2;
    const int wm = (warp >> 1) & 1, wn = warp & 1;

    const __half* b_row = g_wdh + ((size_t)e * D_DIM + col0 + (tid >> 2)) * F_DIM;

    for (int rb2 = blockIdx.x; rb2 * 128 < n_e; rb2 += GRIDX) {
        const int row0 = rb2 * 128;
        int ge = base + row0 + (tid >> 1);
        if (ge > TK - 1) ge = TK - 1;
        const __half* a_row = g_h + (size_t)ge * F_DIM;

        float cc[4][4][4];
        #pragma unroll
        for (int a = 0; a < 4; a++)
            #pragma unroll
            for (int b = 0; b < 4; b++)
                #pragma unroll
                for (int c = 0; c < 4; c++) cc[a][b][c] = 0.f;

        mma_loop(smem0, a_row, b_row, F_DIM / 32, cc);

        if (wk == 0) {
            const int rbase = wm * 64 + (lane >> 2);
            const int colb = col0 + wn * 32 + 2 * (lane & 3);
            #pragma unroll
            for (int mt = 0; mt < 4; mt++) {
                const int r0 = rbase + mt * 16;
                #pragma unroll
                for (int half = 0; half < 2; half++) {
                    const int r = r0 + half * 8;
                    if (row0 + r < n_e) {
                        const int gi = base + row0 + r;
                        const int pos = g_pos[gi];
                        const float wt = g_wt[gi];
                        float* orow = g_o + (size_t)pos * D_DIM;
                        #pragma unroll
                        for (int nt = 0; nt < 4; nt++) {
                            const int col = colb + (nt >> 1) * 16 + (nt & 1) * 8;
                            float2 v;
                            v.x = cc[mt][nt][half * 2 + 0] * wt;
                            v.y = cc[mt][nt][half * 2 + 1] * wt;
                            *(float2*)(orow + col) = v;
                        }
                    }
                }
            }
        }
    }
}

// ---------------- combine the 2 slots per token ----------------
__global__ void combine_kernel(float4* __restrict__ out) {
    const int RD = D_DIM / 4;
    int i = blockIdx.x * blockDim.x + threadIdx.x;
    if (i < T_TOK * RD) {
        int t = i / RD, r = i % RD;
        const float4* go = (const float4*)g_o;
        float4 a = go[(size_t)(2 * t) * RD + r];
        float4 b = go[(size_t)(2 * t + 1) * RD + r];
        out[i] = make_float4(a.x + b.x, a.y + b.y, a.z + b.z, a.w + b.w);
    }
}

// ---------------- launch ----------------
extern "C" void kernel_launch(void* const* d_in, const int* in_sizes, int n_in,
                              void* d_out, int out_size) {
    const float* X   = (const float*)d_in[0];
    const float* rw  = (const float*)d_in[1];
    const float* Wgu = (const float*)d_in[2];
    const float* Wd  = (const float*)d_in[3];
    const void*  sel = d_in[4];
    float* out = (float*)d_out;

    cudaFuncSetAttribute(gemm1_k, cudaFuncAttributeMaxDynamicSharedMemorySize, SMEM_BYTES);
    cudaFuncSetAttribute(gemm2_k, cudaFuncAttributeMaxDynamicSharedMemorySize, SMEM_BYTES);

    cvt_all<<<2048, 256>>>((const float4*)X, (const float4*)Wgu, (const float4*)Wd);
    routing_kernel<<<1, 1024>>>(sel, rw);
    gemm1_k<<<dim3(GRIDX, F_DIM / 32, N_EXP), 256, SMEM_BYTES>>>();
    gemm2_k<<<dim3(GRIDX, D_DIM / 64, N_EXP), 256, SMEM_BYTES>>>();
    combine_kernel<<<(T_TOK * D_DIM / 4 + 255) / 256, 256>>>((float4*)out);
}